// round 15
// baseline (speedup 1.0000x reference)
#include <cuda_runtime.h>
#include <cuda_fp16.h>
#include <cstdint>

// ---------------- problem constants ----------------
#define H   2048
#define F   1408
#define FS  2816
#define E   8
#define T   2048
#define GSTRIDE 2816
#define MAXROWS 7424

// ---------------- GEMM tiling (fp16 mma.sync m16n8k16) ----------------
#define BM  128
#define BN  128
#define BK  64
#define NST 3
#define TILE_BYTES (128 * 144)
#define STAGE_B (2 * TILE_BYTES)
#define SMEM_TOTAL (NST * STAGE_B)    // 110592 B (2 CTAs/SM)

// ---------------- k_mid layout ----------------
#define N_SGT (44 * 16)               // 704 shared-expert gemm1 tiles (first)
#define N_RCV 1024                    // routed gate/up cvt blocks (grid-stride)
#define N_GTH (2 * T)                 // 4096 routed gather blocks
#define NBLK_MID (N_SGT + N_RCV + N_GTH)

// ---------------- device scratch (alloc-free rule) ----------------
// rows [0, T) = shared expert (fixed); routed regions start at T.
__device__ __half g_XG[(size_t)MAXROWS * H];
__device__ __half g_G [(size_t)MAXROWS * GSTRIDE];
__device__ __half g_Y [(size_t)MAXROWS * H];       // fp16 down-proj output
__device__ __half g_rw1 [(size_t)E * 2 * F * H];
__device__ __half g_rsw1[(size_t)2 * FS * H];
__device__ __half g_rwd [(size_t)E * H * F];
__device__ __half g_rswd[(size_t)H * FS];
__device__ int   g_cnt[E];          // zero-init at load; re-zeroed by k_scan each run
__device__ int   g_cursor[E];
__device__ int   g_row0[E + 1];
__device__ int   g_mtiles[E + 1];
__device__ int   g_short[E + 1];
__device__ int   g_rowof[2 * T];
__device__ int   g_tke[2 * T];
__device__ float g_tkw[2 * T];

// ---------------- helpers ----------------
__device__ __forceinline__ uint32_t smem_u32(const void* p) {
    uint32_t a;
    asm("{ .reg .u64 t; cvta.to.shared.u64 t, %1; cvt.u32.u64 %0, t; }" : "=r"(a) : "l"(p));
    return a;
}
__device__ __forceinline__ void cp16(uint32_t s, const void* g) {
    asm volatile("cp.async.cg.shared.global [%0], [%1], 16;" :: "r"(s), "l"(g));
}
__device__ __forceinline__ void ldsm4(uint32_t& r0, uint32_t& r1, uint32_t& r2, uint32_t& r3,
                                      uint32_t a) {
    asm volatile("ldmatrix.sync.aligned.m8n8.x4.shared.b16 {%0,%1,%2,%3}, [%4];"
                 : "=r"(r0), "=r"(r1), "=r"(r2), "=r"(r3) : "r"(a));
}
__device__ __forceinline__ void mma16(float* d, const uint32_t* a, const uint32_t* b) {
    asm volatile(
        "mma.sync.aligned.m16n8k16.row.col.f32.f16.f16.f32 "
        "{%0,%1,%2,%3},{%4,%5,%6,%7},{%8,%9},{%0,%1,%2,%3};"
        : "+f"(d[0]), "+f"(d[1]), "+f"(d[2]), "+f"(d[3])
        : "r"(a[0]), "r"(a[1]), "r"(a[2]), "r"(a[3]), "r"(b[0]), "r"(b[1]));
}
__device__ __forceinline__ uint2 f4_to_h4(float4 v) {
    __half2 lo = __floats2half2_rn(v.x, v.y);
    __half2 hi = __floats2half2_rn(v.z, v.w);
    uint2 r;
    r.x = *(uint32_t*)&lo;
    r.y = *(uint32_t*)&hi;
    return r;
}

// ====================== GEMM core (fp16, m16n8k16, 128x128x64, 3-stage) =============
struct GemmCtx {
    uint32_t sA[NST], sB[NST];
    const __half* gA;
    const __half* gB;
    int ldA, ldB;
};

__device__ __forceinline__ void gemm_fill(const GemmCtx& c, int kt, int st, int tid) {
    const __half* gA = c.gA + kt * BK;
    const __half* gB = c.gB + kt * BK;
#pragma unroll
    for (int i = 0; i < 4; i++) {
        int ch = tid + i * 256;
        int r = ch >> 3, cc = ch & 7;
        cp16(c.sA[st] + r * 144 + cc * 16, gA + (size_t)r * c.ldA + cc * 8);
    }
#pragma unroll
    for (int i = 0; i < 4; i++) {
        int ch = tid + i * 256;
        int r = ch >> 3, cc = ch & 7;
        cp16(c.sB[st] + r * 144 + cc * 16, gB + (size_t)r * c.ldB + cc * 8);
    }
}

// Fragment double-buffered (R14): LDSM for kk+1 before MMAs of kk.
__device__ __forceinline__ void gemm_compute(const GemmCtx& c, int st,
                                             int warpM, int warpN, int lane,
                                             float acc[2][8][4]) {
    uint32_t aBase = c.sA[st] + (warpM * 32 + (lane & 15)) * 144 + ((lane >> 4) << 4);
    uint32_t bBase = c.sB[st] +
                     (warpN * 64 + (lane & 7) + ((lane >> 4) << 3)) * 144 +
                     (((lane >> 3) & 1) << 4);
    uint32_t af[2][2][4], bf[2][8][2];
#pragma unroll
    for (int mt = 0; mt < 2; mt++)
        ldsm4(af[0][mt][0], af[0][mt][1], af[0][mt][2], af[0][mt][3],
              aBase + mt * 16 * 144);
#pragma unroll
    for (int p = 0; p < 4; p++)
        ldsm4(bf[0][2 * p][0], bf[0][2 * p][1], bf[0][2 * p + 1][0], bf[0][2 * p + 1][1],
              bBase + p * 16 * 144);
#pragma unroll
    for (int kk = 0; kk < BK / 16; kk++) {
        int cur = kk & 1, nxt = cur ^ 1;
        if (kk + 1 < BK / 16) {
#pragma unroll
            for (int mt = 0; mt < 2; mt++)
                ldsm4(af[nxt][mt][0], af[nxt][mt][1], af[nxt][mt][2], af[nxt][mt][3],
                      aBase + mt * 16 * 144 + (kk + 1) * 32);
#pragma unroll
            for (int p = 0; p < 4; p++)
                ldsm4(bf[nxt][2 * p][0], bf[nxt][2 * p][1],
                      bf[nxt][2 * p + 1][0], bf[nxt][2 * p + 1][1],
                      bBase + p * 16 * 144 + (kk + 1) * 32);
        }
#pragma unroll
        for (int mt = 0; mt < 2; mt++)
#pragma unroll
            for (int nt = 0; nt < 8; nt++)
                mma16(acc[mt][nt], af[cur][mt], bf[cur][nt]);
    }
}

#define GEMM_MAINLOOP(ctx, KT, tid, act, warpM, warpN, lane, acc)                 \
    {                                                                             \
        gemm_fill(ctx, 0, 0, tid);                                                \
        asm volatile("cp.async.commit_group;");                                   \
        gemm_fill(ctx, 1, 1, tid);                                                \
        asm volatile("cp.async.commit_group;");                                   \
        int st = 0, stf = 2;                                                      \
        for (int kt = 0; kt < (KT); kt++) {                                       \
            asm volatile("cp.async.wait_group 1;");                               \
            __syncthreads();                                                      \
            if (kt + 2 < (KT)) gemm_fill(ctx, kt + 2, stf, tid);                  \
            asm volatile("cp.async.commit_group;");                               \
            if (act) gemm_compute(ctx, st, warpM, warpN, lane, acc);              \
            st = (st == NST - 1) ? 0 : st + 1;                                    \
            stf = (stf == NST - 1) ? 0 : stf + 1;                                 \
        }                                                                         \
    }

// GEMM1 tile (SwiGLU epilogue); used for shared (k_mid) and routed (k_g1r) tiles
__device__ __forceinline__ void gemm1_tile(int grp, int mIdx, int nIdx,
                                           const __half* Bsrc, char* smem, int tid) {
    int nBase = nIdx * BN;
    int aRow = g_row0[grp] + mIdx * BM;
    uint32_t sb = smem_u32(smem);
    int lane = tid & 31, wid = tid >> 5;
    int warpM = wid & 3, warpN = wid >> 2;
    bool shortTile = g_short[grp] && (mIdx == g_mtiles[grp] - 1);
    bool act = !shortTile || warpM < 2;

    GemmCtx c;
#pragma unroll
    for (int s = 0; s < NST; s++) {
        c.sA[s] = sb + s * STAGE_B;
        c.sB[s] = sb + s * STAGE_B + TILE_BYTES;
    }
    c.gA = g_XG + (size_t)aRow * H;      c.ldA = H;
    c.gB = Bsrc + (size_t)nBase * H;     c.ldB = H;

    float acc[2][8][4];
#pragma unroll
    for (int a = 0; a < 2; a++)
#pragma unroll
        for (int b = 0; b < 8; b++)
#pragma unroll
            for (int k = 0; k < 4; k++) acc[a][b][k] = 0.f;

    GEMM_MAINLOOP(c, H / BK, tid, act, warpM, warpN, lane, acc);

    if (act) {
        int g4 = lane >> 2, t4 = lane & 3;
        int fHalf = (nBase >> 1) + warpN * 32;
#pragma unroll
        for (int mt = 0; mt < 2; mt++) {
            int r0 = aRow + warpM * 32 + mt * 16 + g4;
#pragma unroll
            for (int nt = 0; nt < 8; nt++) {
                int f = fHalf + nt * 4 + t4;
                float cg = acc[mt][nt][0], cu = acc[mt][nt][1];
                g_G[(size_t)r0 * GSTRIDE + f] =
                    __float2half_rn(cg / (1.f + __expf(-cg)) * cu);
                cg = acc[mt][nt][2]; cu = acc[mt][nt][3];
                g_G[(size_t)(r0 + 8) * GSTRIDE + f] =
                    __float2half_rn(cg / (1.f + __expf(-cg)) * cu);
            }
        }
    }
}

// ---------------- k_pre: gate (0..511) | shared gather | SHARED gate/up cvt --------
#define NB_GATE (T / 4)
__global__ void __launch_bounds__(128) k_pre(const float* __restrict__ x,
                                             const float* __restrict__ gw,
                                             const float* __restrict__ swg,
                                             const float* __restrict__ swu) {
    int b = blockIdx.x;
    if (b >= NB_GATE && b < NB_GATE + T / 2) {
        int t0 = (b - NB_GATE) * 2;
        const float4* src = (const float4*)(x + (size_t)t0 * H);
        uint2* dst = (uint2*)(g_XG + (size_t)t0 * H);
#pragma unroll
        for (int i = 0; i < 8; i++)
            dst[threadIdx.x + i * 128] = f4_to_h4(src[threadIdx.x + i * 128]);
        return;
    }
    if (b >= NB_GATE) {
        int j2 = b - NB_GATE - T / 2;                 // 0 .. 2*FS-1
        const float* src = ((j2 & 1) ? swu : swg) + (size_t)(j2 >> 1) * H;
        uint2* d = (uint2*)(g_rsw1 + (size_t)j2 * H);
        const float4* s = (const float4*)src;
#pragma unroll
        for (int i = 0; i < 4; i++)
            d[threadIdx.x + i * 128] = f4_to_h4(s[threadIdx.x + i * 128]);
        return;
    }
    int tok = b * 4 + (threadIdx.x >> 5);
    int lane = threadIdx.x & 31;
    const float* xr = x + (size_t)tok * H;
    float xv[H / 32];
#pragma unroll
    for (int i = 0; i < H / 32; i++) xv[i] = xr[lane + i * 32];
    float sc[E];
#pragma unroll
    for (int e = 0; e < E; e++) {
        const float* w = gw + (size_t)e * H;
        float a = 0.f;
#pragma unroll
        for (int i = 0; i < H / 32; i++) a += xv[i] * w[lane + i * 32];
#pragma unroll
        for (int o = 16; o > 0; o >>= 1) a += __shfl_xor_sync(0xffffffffu, a, o);
        sc[e] = a;
    }
    if (lane == 0) {
        float mx = sc[0];
#pragma unroll
        for (int e = 1; e < E; e++) mx = fmaxf(mx, sc[e]);
        float s = 0.f;
#pragma unroll
        for (int e = 0; e < E; e++) { sc[e] = expf(sc[e] - mx); s += sc[e]; }
        float inv_s = 1.f / s;
#pragma unroll
        for (int e = 0; e < E; e++) sc[e] *= inv_s;
        int e0 = 0;
#pragma unroll
        for (int e = 1; e < E; e++) if (sc[e] > sc[e0]) e0 = e;
        int e1 = -1;
#pragma unroll
        for (int e = 0; e < E; e++)
            if (e != e0 && (e1 < 0 || sc[e] > sc[e1])) e1 = e;
        float w0 = sc[e0], w1 = sc[e1];
        float inv = 1.f / (w0 + w1 + 1e-20f);
        g_tke[2 * tok]     = e0;
        g_tke[2 * tok + 1] = e1;
        g_tkw[2 * tok]     = w0 * inv;
        g_tkw[2 * tok + 1] = w1 * inv;
        atomicAdd(&g_cnt[e0], 1);
        atomicAdd(&g_cnt[e1], 1);
    }
}

// ---------------- k_scan (64-row pad; shared at rows [0,T)) ----------------
__global__ void k_scan() {
    if (threadIdx.x == 0 && blockIdx.x == 0) {
        int off = T;
        for (int e = 0; e < E; e++) {
            g_row0[e]   = off;
            g_cursor[e] = off;
            int r64 = (g_cnt[e] + 63) >> 6;
            g_mtiles[e] = (r64 + 1) >> 1;
            g_short[e]  = r64 & 1;
            off += r64 << 6;
            g_cnt[e] = 0;
        }
        g_row0[E]   = 0;
        g_mtiles[E] = T >> 7;
        g_short[E]  = 0;
    }
}

// ---------------- k_mid: shared GEMM1 tiles | routed gate/up cvt | routed gather ----
__global__ void __launch_bounds__(256, 2) k_mid(const float* __restrict__ x,
                                                const float* __restrict__ wg,
                                                const float* __restrict__ wu) {
    int bid = blockIdx.x;
    int tid = threadIdx.x;
    extern __shared__ char smem[];

    if (bid < N_SGT) {
        // shared-expert GEMM1 tile: grp = E (16 m x 44 n)
        gemm1_tile(E, bid & 15, bid >> 4, g_rsw1, smem, tid);
        return;
    }
    if (bid < N_SGT + N_RCV) {
        // routed gate/up cvt: flat float4 grid-stride over interleaved dest rows
        const int n4 = E * 2 * F * (H / 4);            // 11,534,336
        int i0 = (bid - N_SGT) * 256 + tid;
        for (int i = i0; i < n4; i += N_RCV * 256) {
            int row = i >> 9;                          // / (H/4)
            int col = i & 511;
            int grp2 = row / (2 * F);
            int j2 = row - grp2 * 2 * F;
            const float4* s = (const float4*)(((j2 & 1) ? wu : wg) +
                              ((size_t)grp2 * F + (j2 >> 1)) * H);
            ((uint2*)(g_rw1 + (size_t)row * H))[col] = f4_to_h4(s[col]);
        }
        return;
    }
    {
        // routed gather
        __shared__ int sp;
        int b = bid - (N_SGT + N_RCV);
        if (tid == 0) {
            int e = g_tke[b];
            int q = atomicAdd(&g_cursor[e], 1);
            g_rowof[b] = q;
            sp = q;
        }
        __syncthreads();
        int p = sp;
        int t = b >> 1;
        const float4* src = (const float4*)(x + (size_t)t * H);
        uint2* dst = (uint2*)(g_XG + (size_t)p * H);
#pragma unroll
        for (int i = 0; i < 2; i++)
            dst[tid + i * 256] = f4_to_h4(src[tid + i * 256]);
    }
}

// ---------------- k_g1r: routed GEMM1 tiles; x==22 = down-weight cvt slices ---------
__global__ void __launch_bounds__(256, 2) k_g1r(const float* __restrict__ wd,
                                                const float* __restrict__ swd) {
    int grp = blockIdx.z;
    int tid = threadIdx.x;
    extern __shared__ char smem[];
    if (blockIdx.x == 2 * F / BN) {
        const int n1 = E * H * F / 4;
        const int n2 = H * FS / 4;
        const int NB = 32 * E;                          // 256 slices
        int cid = grp * 32 + blockIdx.y;
        int stride = NB * 256;
        for (int i = cid * 256 + tid; i < n1 + n2; i += stride) {
            if (i < n1)
                ((uint2*)g_rwd)[i] = f4_to_h4(((const float4*)wd)[i]);
            else
                ((uint2*)g_rswd)[i - n1] = f4_to_h4(((const float4*)swd)[i - n1]);
        }
        return;
    }
    if ((int)blockIdx.y >= g_mtiles[grp]) return;
    gemm1_tile(grp, blockIdx.y, blockIdx.x,
               g_rw1 + (size_t)grp * 2 * F * H, smem, tid);
}

// ---------------- k_gemm2: G @ Wd^T -> Y (fp16) ----------------
__global__ void __launch_bounds__(256, 2) k_gemm2() {
    int grp = blockIdx.z;
    if ((int)blockIdx.y >= g_mtiles[grp]) return;
    int Kd = (grp < E) ? F : FS;
    const __half* Bd = (grp < E) ? g_rwd + (size_t)grp * H * F : g_rswd;
    int nBase = blockIdx.x * BN;
    int aRow = g_row0[grp] + blockIdx.y * BM;

    extern __shared__ char smem[];
    uint32_t sb = smem_u32(smem);
    int tid = threadIdx.x, lane = tid & 31, wid = tid >> 5;
    int warpM = wid & 3, warpN = wid >> 2;
    bool shortTile = g_short[grp] && ((int)blockIdx.y == g_mtiles[grp] - 1);
    bool act = !shortTile || warpM < 2;

    GemmCtx c;
#pragma unroll
    for (int s = 0; s < NST; s++) {
        c.sA[s] = sb + s * STAGE_B;
        c.sB[s] = sb + s * STAGE_B + TILE_BYTES;
    }
    c.gA = g_G + (size_t)aRow * GSTRIDE;  c.ldA = GSTRIDE;
    c.gB = Bd + (size_t)nBase * Kd;       c.ldB = Kd;

    float acc[2][8][4];
#pragma unroll
    for (int a = 0; a < 2; a++)
#pragma unroll
        for (int b = 0; b < 8; b++)
#pragma unroll
            for (int k = 0; k < 4; k++) acc[a][b][k] = 0.f;

    GEMM_MAINLOOP(c, Kd / BK, tid, act, warpM, warpN, lane, acc);

    if (act) {
        int g4 = lane >> 2, t4 = lane & 3;
#pragma unroll
        for (int mt = 0; mt < 2; mt++) {
            int r0 = aRow + warpM * 32 + mt * 16 + g4;
#pragma unroll
            for (int nt = 0; nt < 8; nt++) {
                int col = nBase + warpN * 64 + nt * 8 + 2 * t4;
                __half2 v0 = __floats2half2_rn(acc[mt][nt][0], acc[mt][nt][1]);
                __half2 v1 = __floats2half2_rn(acc[mt][nt][2], acc[mt][nt][3]);
                *(__half2*)(g_Y + (size_t)r0 * H + col) = v0;
                *(__half2*)(g_Y + (size_t)(r0 + 8) * H + col) = v1;
            }
        }
    }
}

// ---------------- k_comb (fp16 Y; shared row = t) ----------------
__global__ void __launch_bounds__(256) k_comb(float* __restrict__ out) {
    int t = blockIdx.x;
    int r0 = g_rowof[2 * t], r1 = g_rowof[2 * t + 1];
    float w0 = g_tkw[2 * t], w1 = g_tkw[2 * t + 1];
    const uint2* y0 = (const uint2*)(g_Y + (size_t)r0 * H);
    const uint2* y1 = (const uint2*)(g_Y + (size_t)r1 * H);
    const uint2* ys = (const uint2*)(g_Y + (size_t)t * H);
    float4* o = (float4*)(out + (size_t)t * H);
    for (int i = threadIdx.x; i < H / 4; i += blockDim.x) {
        uint2 a = y0[i], b = y1[i], c = ys[i];
        float2 a0 = __half22float2(*(__half2*)&a.x), a1 = __half22float2(*(__half2*)&a.y);
        float2 b0 = __half22float2(*(__half2*)&b.x), b1 = __half22float2(*(__half2*)&b.y);
        float2 c0 = __half22float2(*(__half2*)&c.x), c1 = __half22float2(*(__half2*)&c.y);
        float4 r;
        r.x = fmaf(w0, a0.x, fmaf(w1, b0.x, c0.x));
        r.y = fmaf(w0, a0.y, fmaf(w1, b0.y, c0.y));
        r.z = fmaf(w0, a1.x, fmaf(w1, b1.x, c1.x));
        r.w = fmaf(w0, a1.y, fmaf(w1, b1.y, c1.y));
        o[i] = r;
    }
}

// ---------------- host launcher ----------------
extern "C" void kernel_launch(void* const* d_in, const int* in_sizes, int n_in,
                              void* d_out, int out_size) {
    const float* x   = (const float*)d_in[0];
    const float* gw  = (const float*)d_in[1];
    const float* wg  = (const float*)d_in[2];
    const float* wu  = (const float*)d_in[3];
    const float* wd  = (const float*)d_in[4];
    const float* swg = (const float*)d_in[5];
    const float* swu = (const float*)d_in[6];
    const float* swd = (const float*)d_in[7];
    float* out = (float*)d_out;

    cudaFuncSetAttribute(k_mid,   cudaFuncAttributeMaxDynamicSharedMemorySize, SMEM_TOTAL);
    cudaFuncSetAttribute(k_g1r,   cudaFuncAttributeMaxDynamicSharedMemorySize, SMEM_TOTAL);
    cudaFuncSetAttribute(k_gemm2, cudaFuncAttributeMaxDynamicSharedMemorySize, SMEM_TOTAL);

    // k_pre: [0,512) gate | [512,1536) shared gather | [1536,1536+2FS) shared cvt
    k_pre<<<NB_GATE + T / 2 + 2 * FS, 128>>>(x, gw, swg, swu);
    k_scan<<<1, 1>>>();
    // k_mid: shared gemm1 first (pins slots), then routed cvt + gather in the slack
    k_mid<<<NBLK_MID, 256, SMEM_TOTAL>>>(x, wg, wu);
    // routed gemm1 (+ hidden down-weight cvt)
    k_g1r<<<dim3(2 * F / BN + 1, 32, E), 256, SMEM_TOTAL>>>(wd, swd);
    k_gemm2<<<dim3(H / BN, 32, E + 1), 256, SMEM_TOTAL>>>();
    k_comb<<<T, 256>>>(out);
}

// round 16
// speedup vs baseline: 1.0151x; 1.0151x over previous
#include <cuda_runtime.h>
#include <cuda_fp16.h>
#include <cstdint>

// ---------------- problem constants ----------------
#define H   2048
#define F   1408
#define FS  2816
#define E   8
#define T   2048
#define GSTRIDE 2816
#define MAXROWS 7424

// ---------------- GEMM tiling (fp16 mma.sync m16n8k16) ----------------
#define BM  128
#define BN  128
#define BK  64
#define NST 3
#define TILE_BYTES (128 * 144)
#define STAGE_B (2 * TILE_BYTES)
#define SMEM_TOTAL (NST * STAGE_B)    // 110592 B (2 CTAs/SM)

// ---------------- k_gemm1 mega-dispatch layout (1D, in dispatch order) ----------
#define N_SGT  (44 * 16)              // 704 shared-expert tiles (first: pin slots)
#define N_RCV  1024                   // routed gate/up cvt blocks
#define N_RGT  (E * 22 * 32)          // 5632 routed tiles (bounds-checked)
#define N_DCV  288                    // down-weight cvt blocks (tail filler)
#define S_RCV  N_SGT
#define S_RGT  (S_RCV + N_RCV)
#define S_DCV  (S_RGT + N_RGT)
#define NBLK_G1 (S_DCV + N_DCV)       // 7648

// ---------------- device scratch (alloc-free rule) ----------------
// rows [0, T) = shared expert (fixed); routed regions start at T.
__device__ __half g_XG[(size_t)MAXROWS * H];
__device__ __half g_G [(size_t)MAXROWS * GSTRIDE];
__device__ __half g_Y [(size_t)MAXROWS * H];
__device__ __half g_rw1 [(size_t)E * 2 * F * H];
__device__ __half g_rsw1[(size_t)2 * FS * H];
__device__ __half g_rwd [(size_t)E * H * F];
__device__ __half g_rswd[(size_t)H * FS];
__device__ int   g_cnt[E];
__device__ int   g_cursor[E];
__device__ int   g_row0[E + 1];
__device__ int   g_mtiles[E + 1];
__device__ int   g_short[E + 1];
__device__ int   g_rowof[2 * T];
__device__ int   g_tke[2 * T];
__device__ float g_tkw[2 * T];
__device__ int   g_cvtdone;           // routed cvt completion counter

// ---------------- helpers ----------------
__device__ __forceinline__ uint32_t smem_u32(const void* p) {
    uint32_t a;
    asm("{ .reg .u64 t; cvta.to.shared.u64 t, %1; cvt.u32.u64 %0, t; }" : "=r"(a) : "l"(p));
    return a;
}
__device__ __forceinline__ void cp16(uint32_t s, const void* g) {
    asm volatile("cp.async.cg.shared.global [%0], [%1], 16;" :: "r"(s), "l"(g));
}
__device__ __forceinline__ void ldsm4(uint32_t& r0, uint32_t& r1, uint32_t& r2, uint32_t& r3,
                                      uint32_t a) {
    asm volatile("ldmatrix.sync.aligned.m8n8.x4.shared.b16 {%0,%1,%2,%3}, [%4];"
                 : "=r"(r0), "=r"(r1), "=r"(r2), "=r"(r3) : "r"(a));
}
__device__ __forceinline__ void mma16(float* d, const uint32_t* a, const uint32_t* b) {
    asm volatile(
        "mma.sync.aligned.m16n8k16.row.col.f32.f16.f16.f32 "
        "{%0,%1,%2,%3},{%4,%5,%6,%7},{%8,%9},{%0,%1,%2,%3};"
        : "+f"(d[0]), "+f"(d[1]), "+f"(d[2]), "+f"(d[3])
        : "r"(a[0]), "r"(a[1]), "r"(a[2]), "r"(a[3]), "r"(b[0]), "r"(b[1]));
}
__device__ __forceinline__ uint2 f4_to_h4(float4 v) {
    __half2 lo = __floats2half2_rn(v.x, v.y);
    __half2 hi = __floats2half2_rn(v.z, v.w);
    uint2 r;
    r.x = *(uint32_t*)&lo;
    r.y = *(uint32_t*)&hi;
    return r;
}

// ====================== GEMM core (fp16, m16n8k16, 128x128x64, 3-stage) =============
struct GemmCtx {
    uint32_t sA[NST], sB[NST];
    const __half* gA;
    const __half* gB;
    int ldA, ldB;
};

__device__ __forceinline__ void gemm_fill(const GemmCtx& c, int kt, int st, int tid) {
    const __half* gA = c.gA + kt * BK;
    const __half* gB = c.gB + kt * BK;
#pragma unroll
    for (int i = 0; i < 4; i++) {
        int ch = tid + i * 256;
        int r = ch >> 3, cc = ch & 7;
        cp16(c.sA[st] + r * 144 + cc * 16, gA + (size_t)r * c.ldA + cc * 8);
    }
#pragma unroll
    for (int i = 0; i < 4; i++) {
        int ch = tid + i * 256;
        int r = ch >> 3, cc = ch & 7;
        cp16(c.sB[st] + r * 144 + cc * 16, gB + (size_t)r * c.ldB + cc * 8);
    }
}

// Fragment double-buffered (R14): LDSM for kk+1 before MMAs of kk.
__device__ __forceinline__ void gemm_compute(const GemmCtx& c, int st,
                                             int warpM, int warpN, int lane,
                                             float acc[2][8][4]) {
    uint32_t aBase = c.sA[st] + (warpM * 32 + (lane & 15)) * 144 + ((lane >> 4) << 4);
    uint32_t bBase = c.sB[st] +
                     (warpN * 64 + (lane & 7) + ((lane >> 4) << 3)) * 144 +
                     (((lane >> 3) & 1) << 4);
    uint32_t af[2][2][4], bf[2][8][2];
#pragma unroll
    for (int mt = 0; mt < 2; mt++)
        ldsm4(af[0][mt][0], af[0][mt][1], af[0][mt][2], af[0][mt][3],
              aBase + mt * 16 * 144);
#pragma unroll
    for (int p = 0; p < 4; p++)
        ldsm4(bf[0][2 * p][0], bf[0][2 * p][1], bf[0][2 * p + 1][0], bf[0][2 * p + 1][1],
              bBase + p * 16 * 144);
#pragma unroll
    for (int kk = 0; kk < BK / 16; kk++) {
        int cur = kk & 1, nxt = cur ^ 1;
        if (kk + 1 < BK / 16) {
#pragma unroll
            for (int mt = 0; mt < 2; mt++)
                ldsm4(af[nxt][mt][0], af[nxt][mt][1], af[nxt][mt][2], af[nxt][mt][3],
                      aBase + mt * 16 * 144 + (kk + 1) * 32);
#pragma unroll
            for (int p = 0; p < 4; p++)
                ldsm4(bf[nxt][2 * p][0], bf[nxt][2 * p][1],
                      bf[nxt][2 * p + 1][0], bf[nxt][2 * p + 1][1],
                      bBase + p * 16 * 144 + (kk + 1) * 32);
        }
#pragma unroll
        for (int mt = 0; mt < 2; mt++)
#pragma unroll
            for (int nt = 0; nt < 8; nt++)
                mma16(acc[mt][nt], af[cur][mt], bf[cur][nt]);
    }
}

#define GEMM_MAINLOOP(ctx, KT, tid, act, warpM, warpN, lane, acc)                 \
    {                                                                             \
        gemm_fill(ctx, 0, 0, tid);                                                \
        asm volatile("cp.async.commit_group;");                                   \
        gemm_fill(ctx, 1, 1, tid);                                                \
        asm volatile("cp.async.commit_group;");                                   \
        int st = 0, stf = 2;                                                      \
        for (int kt = 0; kt < (KT); kt++) {                                       \
            asm volatile("cp.async.wait_group 1;");                               \
            __syncthreads();                                                      \
            if (kt + 2 < (KT)) gemm_fill(ctx, kt + 2, stf, tid);                  \
            asm volatile("cp.async.commit_group;");                               \
            if (act) gemm_compute(ctx, st, warpM, warpN, lane, acc);              \
            st = (st == NST - 1) ? 0 : st + 1;                                    \
            stf = (stf == NST - 1) ? 0 : stf + 1;                                 \
        }                                                                         \
    }

// GEMM1 tile body (SwiGLU epilogue)
__device__ __forceinline__ void gemm1_tile(int grp, int mIdx, int nIdx,
                                           const __half* Bsrc, char* smem, int tid) {
    int nBase = nIdx * BN;
    int aRow = g_row0[grp] + mIdx * BM;
    uint32_t sb = smem_u32(smem);
    int lane = tid & 31, wid = tid >> 5;
    int warpM = wid & 3, warpN = wid >> 2;
    bool shortTile = g_short[grp] && (mIdx == g_mtiles[grp] - 1);
    bool act = !shortTile || warpM < 2;

    GemmCtx c;
#pragma unroll
    for (int s = 0; s < NST; s++) {
        c.sA[s] = sb + s * STAGE_B;
        c.sB[s] = sb + s * STAGE_B + TILE_BYTES;
    }
    c.gA = g_XG + (size_t)aRow * H;      c.ldA = H;
    c.gB = Bsrc + (size_t)nBase * H;     c.ldB = H;

    float acc[2][8][4];
#pragma unroll
    for (int a = 0; a < 2; a++)
#pragma unroll
        for (int b = 0; b < 8; b++)
#pragma unroll
            for (int k = 0; k < 4; k++) acc[a][b][k] = 0.f;

    GEMM_MAINLOOP(c, H / BK, tid, act, warpM, warpN, lane, acc);

    if (act) {
        int g4 = lane >> 2, t4 = lane & 3;
        int fHalf = (nBase >> 1) + warpN * 32;
#pragma unroll
        for (int mt = 0; mt < 2; mt++) {
            int r0 = aRow + warpM * 32 + mt * 16 + g4;
#pragma unroll
            for (int nt = 0; nt < 8; nt++) {
                int f = fHalf + nt * 4 + t4;
                float cg = acc[mt][nt][0], cu = acc[mt][nt][1];
                g_G[(size_t)r0 * GSTRIDE + f] =
                    __float2half_rn(cg / (1.f + __expf(-cg)) * cu);
                cg = acc[mt][nt][2]; cu = acc[mt][nt][3];
                g_G[(size_t)(r0 + 8) * GSTRIDE + f] =
                    __float2half_rn(cg / (1.f + __expf(-cg)) * cu);
            }
        }
    }
}

// ---------------- k_pre: gate (0..511) | shared gather | SHARED gate/up cvt --------
#define NB_GATE (T / 4)
__global__ void __launch_bounds__(128) k_pre(const float* __restrict__ x,
                                             const float* __restrict__ gw,
                                             const float* __restrict__ swg,
                                             const float* __restrict__ swu) {
    int b = blockIdx.x;
    if (b >= NB_GATE && b < NB_GATE + T / 2) {
        int t0 = (b - NB_GATE) * 2;
        const float4* src = (const float4*)(x + (size_t)t0 * H);
        uint2* dst = (uint2*)(g_XG + (size_t)t0 * H);
#pragma unroll
        for (int i = 0; i < 8; i++)
            dst[threadIdx.x + i * 128] = f4_to_h4(src[threadIdx.x + i * 128]);
        return;
    }
    if (b >= NB_GATE) {
        int j2 = b - NB_GATE - T / 2;                 // 0 .. 2*FS-1
        const float* src = ((j2 & 1) ? swu : swg) + (size_t)(j2 >> 1) * H;
        uint2* d = (uint2*)(g_rsw1 + (size_t)j2 * H);
        const float4* s = (const float4*)src;
#pragma unroll
        for (int i = 0; i < 4; i++)
            d[threadIdx.x + i * 128] = f4_to_h4(s[threadIdx.x + i * 128]);
        return;
    }
    int tok = b * 4 + (threadIdx.x >> 5);
    int lane = threadIdx.x & 31;
    const float* xr = x + (size_t)tok * H;
    float xv[H / 32];
#pragma unroll
    for (int i = 0; i < H / 32; i++) xv[i] = xr[lane + i * 32];
    float sc[E];
#pragma unroll
    for (int e = 0; e < E; e++) {
        const float* w = gw + (size_t)e * H;
        float a = 0.f;
#pragma unroll
        for (int i = 0; i < H / 32; i++) a += xv[i] * w[lane + i * 32];
#pragma unroll
        for (int o = 16; o > 0; o >>= 1) a += __shfl_xor_sync(0xffffffffu, a, o);
        sc[e] = a;
    }
    if (lane == 0) {
        float mx = sc[0];
#pragma unroll
        for (int e = 1; e < E; e++) mx = fmaxf(mx, sc[e]);
        float s = 0.f;
#pragma unroll
        for (int e = 0; e < E; e++) { sc[e] = expf(sc[e] - mx); s += sc[e]; }
        float inv_s = 1.f / s;
#pragma unroll
        for (int e = 0; e < E; e++) sc[e] *= inv_s;
        int e0 = 0;
#pragma unroll
        for (int e = 1; e < E; e++) if (sc[e] > sc[e0]) e0 = e;
        int e1 = -1;
#pragma unroll
        for (int e = 0; e < E; e++)
            if (e != e0 && (e1 < 0 || sc[e] > sc[e1])) e1 = e;
        float w0 = sc[e0], w1 = sc[e1];
        float inv = 1.f / (w0 + w1 + 1e-20f);
        g_tke[2 * tok]     = e0;
        g_tke[2 * tok + 1] = e1;
        g_tkw[2 * tok]     = w0 * inv;
        g_tkw[2 * tok + 1] = w1 * inv;
        atomicAdd(&g_cnt[e0], 1);
        atomicAdd(&g_cnt[e1], 1);
    }
}

// ---------------- k_scan (64-row pad; shared at rows [0,T); reset cvt counter) ------
__global__ void k_scan() {
    if (threadIdx.x == 0 && blockIdx.x == 0) {
        int off = T;
        for (int e = 0; e < E; e++) {
            g_row0[e]   = off;
            g_cursor[e] = off;
            int r64 = (g_cnt[e] + 63) >> 6;
            g_mtiles[e] = (r64 + 1) >> 1;
            g_short[e]  = r64 & 1;
            off += r64 << 6;
            g_cnt[e] = 0;
        }
        g_row0[E]   = 0;
        g_mtiles[E] = T >> 7;
        g_short[E]  = 0;
        g_cvtdone   = 0;
    }
}

// ---------------- k_gather: routed rows ----------------
__global__ void __launch_bounds__(256) k_gather(const float* __restrict__ x) {
    __shared__ int sp;
    int b = blockIdx.x;
    if (threadIdx.x == 0) {
        int e = g_tke[b];
        int q = atomicAdd(&g_cursor[e], 1);
        g_rowof[b] = q;
        sp = q;
    }
    __syncthreads();
    int p = sp;
    int t = b >> 1;
    const float4* src = (const float4*)(x + (size_t)t * H);
    uint2* dst = (uint2*)(g_XG + (size_t)p * H);
#pragma unroll
    for (int i = 0; i < 2; i++)
        dst[threadIdx.x + i * 256] = f4_to_h4(src[threadIdx.x + i * 256]);
}

// -------- k_gemm1 mega: [shared tiles | routed cvt | routed tiles | down cvt] -------
__global__ void __launch_bounds__(256, 2) k_gemm1(const float* __restrict__ wg,
                                                  const float* __restrict__ wu,
                                                  const float* __restrict__ wd,
                                                  const float* __restrict__ swd) {
    int bid = blockIdx.x;
    int tid = threadIdx.x;
    extern __shared__ char smem[];

    if (bid < N_SGT) {
        // shared-expert tile: grp = E (16 m x 44 n), inputs ready from k_pre
        gemm1_tile(E, bid & 15, bid >> 4, g_rsw1, smem, tid);
        return;
    }
    if (bid < S_RGT) {
        // routed gate/up cvt, grid-stride; runs in shared-phase slack
        const int n4 = E * 2 * F * (H / 4);
        int i0 = (bid - S_RCV) * 256 + tid;
        for (int i = i0; i < n4; i += N_RCV * 256) {
            int row = i >> 9;
            int col = i & 511;
            int grp2 = row / (2 * F);
            int j2 = row - grp2 * 2 * F;
            const float4* s = (const float4*)(((j2 & 1) ? wu : wg) +
                              ((size_t)grp2 * F + (j2 >> 1)) * H);
            ((uint2*)(g_rw1 + (size_t)row * H))[col] = f4_to_h4(s[col]);
        }
        __threadfence();
        __syncthreads();
        if (tid == 0) atomicAdd(&g_cvtdone, 1);
        return;
    }
    if (bid < S_DCV) {
        // routed tile; guard on cvt completion (spin ~never engages: cvt is
        // dispatched earlier and completes during the shared-tile phase)
        int idx = bid - S_RGT;
        int grp = idx / (22 * 32);
        int rem = idx - grp * (22 * 32);
        int nIdx = rem >> 5, mIdx = rem & 31;
        if (mIdx >= g_mtiles[grp]) return;
        if (tid == 0) {
            volatile int* p = &g_cvtdone;
            while (*p < N_RCV) __nanosleep(200);
        }
        __syncthreads();
        gemm1_tile(grp, mIdx, nIdx, g_rw1 + (size_t)grp * 2 * F * H, smem, tid);
        return;
    }
    {
        // down-weight cvt (consumed by k_gemm2 next launch)
        const int n1 = E * H * F / 4;
        const int n2 = H * FS / 4;
        int cid = bid - S_DCV;
        int stride = N_DCV * 256;
        for (int i = cid * 256 + tid; i < n1 + n2; i += stride) {
            if (i < n1)
                ((uint2*)g_rwd)[i] = f4_to_h4(((const float4*)wd)[i]);
            else
                ((uint2*)g_rswd)[i - n1] = f4_to_h4(((const float4*)swd)[i - n1]);
        }
    }
}

// ---------------- k_gemm2: G @ Wd^T -> Y (fp16) ----------------
__global__ void __launch_bounds__(256, 2) k_gemm2() {
    int grp = blockIdx.z;
    if ((int)blockIdx.y >= g_mtiles[grp]) return;
    int Kd = (grp < E) ? F : FS;
    const __half* Bd = (grp < E) ? g_rwd + (size_t)grp * H * F : g_rswd;
    int nBase = blockIdx.x * BN;
    int aRow = g_row0[grp] + blockIdx.y * BM;

    extern __shared__ char smem[];
    uint32_t sb = smem_u32(smem);
    int tid = threadIdx.x, lane = tid & 31, wid = tid >> 5;
    int warpM = wid & 3, warpN = wid >> 2;
    bool shortTile = g_short[grp] && ((int)blockIdx.y == g_mtiles[grp] - 1);
    bool act = !shortTile || warpM < 2;

    GemmCtx c;
#pragma unroll
    for (int s = 0; s < NST; s++) {
        c.sA[s] = sb + s * STAGE_B;
        c.sB[s] = sb + s * STAGE_B + TILE_BYTES;
    }
    c.gA = g_G + (size_t)aRow * GSTRIDE;  c.ldA = GSTRIDE;
    c.gB = Bd + (size_t)nBase * Kd;       c.ldB = Kd;

    float acc[2][8][4];
#pragma unroll
    for (int a = 0; a < 2; a++)
#pragma unroll
        for (int b = 0; b < 8; b++)
#pragma unroll
            for (int k = 0; k < 4; k++) acc[a][b][k] = 0.f;

    GEMM_MAINLOOP(c, Kd / BK, tid, act, warpM, warpN, lane, acc);

    if (act) {
        int g4 = lane >> 2, t4 = lane & 3;
#pragma unroll
        for (int mt = 0; mt < 2; mt++) {
            int r0 = aRow + warpM * 32 + mt * 16 + g4;
#pragma unroll
            for (int nt = 0; nt < 8; nt++) {
                int col = nBase + warpN * 64 + nt * 8 + 2 * t4;
                __half2 v0 = __floats2half2_rn(acc[mt][nt][0], acc[mt][nt][1]);
                __half2 v1 = __floats2half2_rn(acc[mt][nt][2], acc[mt][nt][3]);
                *(__half2*)(g_Y + (size_t)r0 * H + col) = v0;
                *(__half2*)(g_Y + (size_t)(r0 + 8) * H + col) = v1;
            }
        }
    }
}

// ---------------- k_comb (fp16 Y; shared row = t) ----------------
__global__ void __launch_bounds__(256) k_comb(float* __restrict__ out) {
    int t = blockIdx.x;
    int r0 = g_rowof[2 * t], r1 = g_rowof[2 * t + 1];
    float w0 = g_tkw[2 * t], w1 = g_tkw[2 * t + 1];
    const uint2* y0 = (const uint2*)(g_Y + (size_t)r0 * H);
    const uint2* y1 = (const uint2*)(g_Y + (size_t)r1 * H);
    const uint2* ys = (const uint2*)(g_Y + (size_t)t * H);
    float4* o = (float4*)(out + (size_t)t * H);
    for (int i = threadIdx.x; i < H / 4; i += blockDim.x) {
        uint2 a = y0[i], b = y1[i], c = ys[i];
        float2 a0 = __half22float2(*(__half2*)&a.x), a1 = __half22float2(*(__half2*)&a.y);
        float2 b0 = __half22float2(*(__half2*)&b.x), b1 = __half22float2(*(__half2*)&b.y);
        float2 c0 = __half22float2(*(__half2*)&c.x), c1 = __half22float2(*(__half2*)&c.y);
        float4 r;
        r.x = fmaf(w0, a0.x, fmaf(w1, b0.x, c0.x));
        r.y = fmaf(w0, a0.y, fmaf(w1, b0.y, c0.y));
        r.z = fmaf(w0, a1.x, fmaf(w1, b1.x, c1.x));
        r.w = fmaf(w0, a1.y, fmaf(w1, b1.y, c1.y));
        o[i] = r;
    }
}

// ---------------- host launcher ----------------
extern "C" void kernel_launch(void* const* d_in, const int* in_sizes, int n_in,
                              void* d_out, int out_size) {
    const float* x   = (const float*)d_in[0];
    const float* gw  = (const float*)d_in[1];
    const float* wg  = (const float*)d_in[2];
    const float* wu  = (const float*)d_in[3];
    const float* wd  = (const float*)d_in[4];
    const float* swg = (const float*)d_in[5];
    const float* swu = (const float*)d_in[6];
    const float* swd = (const float*)d_in[7];
    float* out = (float*)d_out;

    cudaFuncSetAttribute(k_gemm1, cudaFuncAttributeMaxDynamicSharedMemorySize, SMEM_TOTAL);
    cudaFuncSetAttribute(k_gemm2, cudaFuncAttributeMaxDynamicSharedMemorySize, SMEM_TOTAL);

    // k_pre: [0,512) gate | [512,1536) shared gather | [1536,1536+2FS) shared cvt
    k_pre<<<NB_GATE + T / 2 + 2 * FS, 128>>>(x, gw, swg, swu);
    k_scan<<<1, 1>>>();
    k_gather<<<2 * T, 256>>>(x);
    k_gemm1<<<NBLK_G1, 256, SMEM_TOTAL>>>(wg, wu, wd, swd);
    k_gemm2<<<dim3(H / BN, 32, E + 1), 256, SMEM_TOTAL>>>();
    k_comb<<<T, 256>>>(out);
}

// round 17
// speedup vs baseline: 1.0388x; 1.0234x over previous
#include <cuda_runtime.h>
#include <cuda_fp16.h>
#include <cstdint>

// ---------------- problem constants ----------------
#define H   2048
#define F   1408
#define FS  2816
#define E   8
#define T   2048
#define GSTRIDE 2816
#define MAXROWS 7424

// ---------------- GEMM tiling (fp16 mma.sync m16n8k16) ----------------
#define BM  128
#define BN  128
#define BK  64
#define NST 3
#define TILE_BYTES (128 * 144)
#define STAGE_B (2 * TILE_BYTES)
#define SMEM_TOTAL (NST * STAGE_B)    // 110592 B (2 CTAs/SM)

// ---------------- device scratch (alloc-free rule) ----------------
// rows [0, T) = shared expert (fixed); routed regions start at T.
__device__ __half g_XG[(size_t)MAXROWS * H];
__device__ __half g_G [(size_t)MAXROWS * GSTRIDE];
__device__ __half g_Y [(size_t)MAXROWS * H];
__device__ __half g_rw1 [(size_t)E * 2 * F * H];
__device__ __half g_rsw1[(size_t)2 * FS * H];
__device__ __half g_rwd [(size_t)E * H * F];
__device__ __half g_rswd[(size_t)H * FS];
__device__ int   g_cnt[E];
__device__ int   g_cursor[E];
__device__ int   g_row0[E + 1];
__device__ int   g_mtiles[E + 1];
__device__ int   g_short[E + 1];
__device__ int   g_rowof[2 * T];
__device__ int   g_tke[2 * T];
__device__ float g_tkw[2 * T];

// ---------------- helpers ----------------
__device__ __forceinline__ uint32_t smem_u32(const void* p) {
    uint32_t a;
    asm("{ .reg .u64 t; cvta.to.shared.u64 t, %1; cvt.u32.u64 %0, t; }" : "=r"(a) : "l"(p));
    return a;
}
__device__ __forceinline__ void cp16(uint32_t s, const void* g) {
    asm volatile("cp.async.cg.shared.global [%0], [%1], 16;" :: "r"(s), "l"(g));
}
__device__ __forceinline__ void ldsm4(uint32_t& r0, uint32_t& r1, uint32_t& r2, uint32_t& r3,
                                      uint32_t a) {
    asm volatile("ldmatrix.sync.aligned.m8n8.x4.shared.b16 {%0,%1,%2,%3}, [%4];"
                 : "=r"(r0), "=r"(r1), "=r"(r2), "=r"(r3) : "r"(a));
}
__device__ __forceinline__ void mma16(float* d, const uint32_t* a, const uint32_t* b) {
    asm volatile(
        "mma.sync.aligned.m16n8k16.row.col.f32.f16.f16.f32 "
        "{%0,%1,%2,%3},{%4,%5,%6,%7},{%8,%9},{%0,%1,%2,%3};"
        : "+f"(d[0]), "+f"(d[1]), "+f"(d[2]), "+f"(d[3])
        : "r"(a[0]), "r"(a[1]), "r"(a[2]), "r"(a[3]), "r"(b[0]), "r"(b[1]));
}
__device__ __forceinline__ uint2 f4_to_h4(float4 v) {
    __half2 lo = __floats2half2_rn(v.x, v.y);
    __half2 hi = __floats2half2_rn(v.z, v.w);
    uint2 r;
    r.x = *(uint32_t*)&lo;
    r.y = *(uint32_t*)&hi;
    return r;
}

// ====================== GEMM core (fp16, m16n8k16, 128x128x64, 3-stage) =============
struct GemmCtx {
    uint32_t sA[NST], sB[NST];
    const __half* gA;
    const __half* gB;
    int ldA, ldB;
};

__device__ __forceinline__ void gemm_fill(const GemmCtx& c, int kt, int st, int tid) {
    const __half* gA = c.gA + kt * BK;
    const __half* gB = c.gB + kt * BK;
#pragma unroll
    for (int i = 0; i < 4; i++) {
        int ch = tid + i * 256;
        int r = ch >> 3, cc = ch & 7;
        cp16(c.sA[st] + r * 144 + cc * 16, gA + (size_t)r * c.ldA + cc * 8);
    }
#pragma unroll
    for (int i = 0; i < 4; i++) {
        int ch = tid + i * 256;
        int r = ch >> 3, cc = ch & 7;
        cp16(c.sB[st] + r * 144 + cc * 16, gB + (size_t)r * c.ldB + cc * 8);
    }
}

// Fragment double-buffered (R14): LDSM for kk+1 before MMAs of kk.
__device__ __forceinline__ void gemm_compute(const GemmCtx& c, int st,
                                             int warpM, int warpN, int lane,
                                             float acc[2][8][4]) {
    uint32_t aBase = c.sA[st] + (warpM * 32 + (lane & 15)) * 144 + ((lane >> 4) << 4);
    uint32_t bBase = c.sB[st] +
                     (warpN * 64 + (lane & 7) + ((lane >> 4) << 3)) * 144 +
                     (((lane >> 3) & 1) << 4);
    uint32_t af[2][2][4], bf[2][8][2];
#pragma unroll
    for (int mt = 0; mt < 2; mt++)
        ldsm4(af[0][mt][0], af[0][mt][1], af[0][mt][2], af[0][mt][3],
              aBase + mt * 16 * 144);
#pragma unroll
    for (int p = 0; p < 4; p++)
        ldsm4(bf[0][2 * p][0], bf[0][2 * p][1], bf[0][2 * p + 1][0], bf[0][2 * p + 1][1],
              bBase + p * 16 * 144);
#pragma unroll
    for (int kk = 0; kk < BK / 16; kk++) {
        int cur = kk & 1, nxt = cur ^ 1;
        if (kk + 1 < BK / 16) {
#pragma unroll
            for (int mt = 0; mt < 2; mt++)
                ldsm4(af[nxt][mt][0], af[nxt][mt][1], af[nxt][mt][2], af[nxt][mt][3],
                      aBase + mt * 16 * 144 + (kk + 1) * 32);
#pragma unroll
            for (int p = 0; p < 4; p++)
                ldsm4(bf[nxt][2 * p][0], bf[nxt][2 * p][1],
                      bf[nxt][2 * p + 1][0], bf[nxt][2 * p + 1][1],
                      bBase + p * 16 * 144 + (kk + 1) * 32);
        }
#pragma unroll
        for (int mt = 0; mt < 2; mt++)
#pragma unroll
            for (int nt = 0; nt < 8; nt++)
                mma16(acc[mt][nt], af[cur][mt], bf[cur][nt]);
    }
}

#define GEMM_MAINLOOP(ctx, KT, tid, act, warpM, warpN, lane, acc)                 \
    {                                                                             \
        gemm_fill(ctx, 0, 0, tid);                                                \
        asm volatile("cp.async.commit_group;");                                   \
        gemm_fill(ctx, 1, 1, tid);                                                \
        asm volatile("cp.async.commit_group;");                                   \
        int st = 0, stf = 2;                                                      \
        for (int kt = 0; kt < (KT); kt++) {                                       \
            asm volatile("cp.async.wait_group 1;");                               \
            __syncthreads();                                                      \
            if (kt + 2 < (KT)) gemm_fill(ctx, kt + 2, stf, tid);                  \
            asm volatile("cp.async.commit_group;");                               \
            if (act) gemm_compute(ctx, st, warpM, warpN, lane, acc);              \
            st = (st == NST - 1) ? 0 : st + 1;                                    \
            stf = (stf == NST - 1) ? 0 : stf + 1;                                 \
        }                                                                         \
    }

// ---------------- k_gate: gating only (fp32 exact) ----------------
__global__ void __launch_bounds__(128) k_gate(const float* __restrict__ x,
                                              const float* __restrict__ gw) {
    int tok = blockIdx.x * 4 + (threadIdx.x >> 5);
    int lane = threadIdx.x & 31;
    const float* xr = x + (size_t)tok * H;
    float xv[H / 32];
#pragma unroll
    for (int i = 0; i < H / 32; i++) xv[i] = xr[lane + i * 32];
    float sc[E];
#pragma unroll
    for (int e = 0; e < E; e++) {
        const float* w = gw + (size_t)e * H;
        float a = 0.f;
#pragma unroll
        for (int i = 0; i < H / 32; i++) a += xv[i] * w[lane + i * 32];
#pragma unroll
        for (int o = 16; o > 0; o >>= 1) a += __shfl_xor_sync(0xffffffffu, a, o);
        sc[e] = a;
    }
    if (lane == 0) {
        float mx = sc[0];
#pragma unroll
        for (int e = 1; e < E; e++) mx = fmaxf(mx, sc[e]);
        float s = 0.f;
#pragma unroll
        for (int e = 0; e < E; e++) { sc[e] = expf(sc[e] - mx); s += sc[e]; }
        float inv_s = 1.f / s;
#pragma unroll
        for (int e = 0; e < E; e++) sc[e] *= inv_s;
        int e0 = 0;
#pragma unroll
        for (int e = 1; e < E; e++) if (sc[e] > sc[e0]) e0 = e;
        int e1 = -1;
#pragma unroll
        for (int e = 0; e < E; e++)
            if (e != e0 && (e1 < 0 || sc[e] > sc[e1])) e1 = e;
        float w0 = sc[e0], w1 = sc[e1];
        float inv = 1.f / (w0 + w1 + 1e-20f);
        g_tke[2 * tok]     = e0;
        g_tke[2 * tok + 1] = e1;
        g_tkw[2 * tok]     = w0 * inv;
        g_tkw[2 * tok + 1] = w1 * inv;
        atomicAdd(&g_cnt[e0], 1);
        atomicAdd(&g_cnt[e1], 1);
    }
}

// ------- k_cvtA (side stream): shared gather | shared gate/up cvt | routed cvt -----
#define NB_SHG (T / 2)                 // 1024
#define NB_SCV (2 * FS)                // 5632
#define NB_RCV (E * 2 * F)             // 22528
__global__ void __launch_bounds__(128) k_cvtA(const float* __restrict__ x,
                                              const float* __restrict__ wg,
                                              const float* __restrict__ wu,
                                              const float* __restrict__ swg,
                                              const float* __restrict__ swu) {
    int b = blockIdx.x;
    if (b < NB_SHG) {
        int t0 = b * 2;
        const float4* src = (const float4*)(x + (size_t)t0 * H);
        uint2* dst = (uint2*)(g_XG + (size_t)t0 * H);
#pragma unroll
        for (int i = 0; i < 8; i++)
            dst[threadIdx.x + i * 128] = f4_to_h4(src[threadIdx.x + i * 128]);
        return;
    }
    const float* src;
    __half* dstp;
    if (b < NB_SHG + NB_SCV) {
        int j2 = b - NB_SHG;
        src = ((j2 & 1) ? swu : swg) + (size_t)(j2 >> 1) * H;
        dstp = g_rsw1 + (size_t)j2 * H;
    } else {
        int j = b - NB_SHG - NB_SCV;
        int grp2 = j / (2 * F);
        int j2 = j - grp2 * 2 * F;
        src = ((j2 & 1) ? wu : wg) + ((size_t)grp2 * F + (j2 >> 1)) * H;
        dstp = g_rw1 + (size_t)j * H;
    }
    uint2* d = (uint2*)dstp;
    const float4* s = (const float4*)src;
#pragma unroll
    for (int i = 0; i < 4; i++)
        d[threadIdx.x + i * 128] = f4_to_h4(s[threadIdx.x + i * 128]);
}

// ---------------- k_cvtB (side stream): down-proj weights ----------------
__global__ void __launch_bounds__(256) k_cvtB(const float* __restrict__ wd,
                                              const float* __restrict__ swd) {
    const int n1 = E * H * F / 4;
    const int n2 = H * FS / 4;
    int stride = gridDim.x * 256;
    for (int i = blockIdx.x * 256 + threadIdx.x; i < n1 + n2; i += stride) {
        if (i < n1)
            ((uint2*)g_rwd)[i] = f4_to_h4(((const float4*)wd)[i]);
        else
            ((uint2*)g_rswd)[i - n1] = f4_to_h4(((const float4*)swd)[i - n1]);
    }
}

// ---------------- k_scan (64-row pad; shared at rows [0,T)) ----------------
__global__ void k_scan() {
    if (threadIdx.x == 0 && blockIdx.x == 0) {
        int off = T;
        for (int e = 0; e < E; e++) {
            g_row0[e]   = off;
            g_cursor[e] = off;
            int r64 = (g_cnt[e] + 63) >> 6;
            g_mtiles[e] = (r64 + 1) >> 1;
            g_short[e]  = r64 & 1;
            off += r64 << 6;
            g_cnt[e] = 0;
        }
        g_row0[E]   = 0;
        g_mtiles[E] = T >> 7;
        g_short[E]  = 0;
    }
}

// ---------------- k_gather: routed rows ----------------
__global__ void __launch_bounds__(256) k_gather(const float* __restrict__ x) {
    __shared__ int sp;
    int b = blockIdx.x;
    if (threadIdx.x == 0) {
        int e = g_tke[b];
        int q = atomicAdd(&g_cursor[e], 1);
        g_rowof[b] = q;
        sp = q;
    }
    __syncthreads();
    int p = sp;
    int t = b >> 1;
    const float4* src = (const float4*)(x + (size_t)t * H);
    uint2* dst = (uint2*)(g_XG + (size_t)p * H);
#pragma unroll
    for (int i = 0; i < 2; i++)
        dst[threadIdx.x + i * 256] = f4_to_h4(src[threadIdx.x + i * 256]);
}

// ---------------- k_gemm1: pure GEMM tiles (shared + routed), SwiGLU epilogue -------
__global__ void __launch_bounds__(256, 2) k_gemm1() {
    int grp = blockIdx.z;
    if ((int)blockIdx.y >= g_mtiles[grp]) return;
    int N2 = (grp < E) ? 2 * F : 2 * FS;
    int nBase = blockIdx.x * BN;
    if (nBase >= N2) return;
    const __half* Bsrc = (grp < E) ? g_rw1 + (size_t)grp * 2 * F * H : g_rsw1;
    int aRow = g_row0[grp] + blockIdx.y * BM;

    extern __shared__ char smem[];
    uint32_t sb = smem_u32(smem);
    int tid = threadIdx.x, lane = tid & 31, wid = tid >> 5;
    int warpM = wid & 3, warpN = wid >> 2;
    bool shortTile = g_short[grp] && ((int)blockIdx.y == g_mtiles[grp] - 1);
    bool act = !shortTile || warpM < 2;

    GemmCtx c;
#pragma unroll
    for (int s = 0; s < NST; s++) {
        c.sA[s] = sb + s * STAGE_B;
        c.sB[s] = sb + s * STAGE_B + TILE_BYTES;
    }
    c.gA = g_XG + (size_t)aRow * H;      c.ldA = H;
    c.gB = Bsrc + (size_t)nBase * H;     c.ldB = H;

    float acc[2][8][4];
#pragma unroll
    for (int a = 0; a < 2; a++)
#pragma unroll
        for (int b = 0; b < 8; b++)
#pragma unroll
            for (int k = 0; k < 4; k++) acc[a][b][k] = 0.f;

    GEMM_MAINLOOP(c, H / BK, tid, act, warpM, warpN, lane, acc);

    if (act) {
        int g4 = lane >> 2, t4 = lane & 3;
        int fHalf = (nBase >> 1) + warpN * 32;
#pragma unroll
        for (int mt = 0; mt < 2; mt++) {
            int r0 = aRow + warpM * 32 + mt * 16 + g4;
#pragma unroll
            for (int nt = 0; nt < 8; nt++) {
                int f = fHalf + nt * 4 + t4;
                float cg = acc[mt][nt][0], cu = acc[mt][nt][1];
                g_G[(size_t)r0 * GSTRIDE + f] =
                    __float2half_rn(cg / (1.f + __expf(-cg)) * cu);
                cg = acc[mt][nt][2]; cu = acc[mt][nt][3];
                g_G[(size_t)(r0 + 8) * GSTRIDE + f] =
                    __float2half_rn(cg / (1.f + __expf(-cg)) * cu);
            }
        }
    }
}

// ---------------- k_gemm2: G @ Wd^T -> Y (fp16) ----------------
__global__ void __launch_bounds__(256, 2) k_gemm2() {
    int grp = blockIdx.z;
    if ((int)blockIdx.y >= g_mtiles[grp]) return;
    int Kd = (grp < E) ? F : FS;
    const __half* Bd = (grp < E) ? g_rwd + (size_t)grp * H * F : g_rswd;
    int nBase = blockIdx.x * BN;
    int aRow = g_row0[grp] + blockIdx.y * BM;

    extern __shared__ char smem[];
    uint32_t sb = smem_u32(smem);
    int tid = threadIdx.x, lane = tid & 31, wid = tid >> 5;
    int warpM = wid & 3, warpN = wid >> 2;
    bool shortTile = g_short[grp] && ((int)blockIdx.y == g_mtiles[grp] - 1);
    bool act = !shortTile || warpM < 2;

    GemmCtx c;
#pragma unroll
    for (int s = 0; s < NST; s++) {
        c.sA[s] = sb + s * STAGE_B;
        c.sB[s] = sb + s * STAGE_B + TILE_BYTES;
    }
    c.gA = g_G + (size_t)aRow * GSTRIDE;  c.ldA = GSTRIDE;
    c.gB = Bd + (size_t)nBase * Kd;       c.ldB = Kd;

    float acc[2][8][4];
#pragma unroll
    for (int a = 0; a < 2; a++)
#pragma unroll
        for (int b = 0; b < 8; b++)
#pragma unroll
            for (int k = 0; k < 4; k++) acc[a][b][k] = 0.f;

    GEMM_MAINLOOP(c, Kd / BK, tid, act, warpM, warpN, lane, acc);

    if (act) {
        int g4 = lane >> 2, t4 = lane & 3;
#pragma unroll
        for (int mt = 0; mt < 2; mt++) {
            int r0 = aRow + warpM * 32 + mt * 16 + g4;
#pragma unroll
            for (int nt = 0; nt < 8; nt++) {
                int col = nBase + warpN * 64 + nt * 8 + 2 * t4;
                __half2 v0 = __floats2half2_rn(acc[mt][nt][0], acc[mt][nt][1]);
                __half2 v1 = __floats2half2_rn(acc[mt][nt][2], acc[mt][nt][3]);
                *(__half2*)(g_Y + (size_t)r0 * H + col) = v0;
                *(__half2*)(g_Y + (size_t)(r0 + 8) * H + col) = v1;
            }
        }
    }
}

// ---------------- k_comb (fp16 Y; shared row = t) ----------------
__global__ void __launch_bounds__(256) k_comb(float* __restrict__ out) {
    int t = blockIdx.x;
    int r0 = g_rowof[2 * t], r1 = g_rowof[2 * t + 1];
    float w0 = g_tkw[2 * t], w1 = g_tkw[2 * t + 1];
    const uint2* y0 = (const uint2*)(g_Y + (size_t)r0 * H);
    const uint2* y1 = (const uint2*)(g_Y + (size_t)r1 * H);
    const uint2* ys = (const uint2*)(g_Y + (size_t)t * H);
    float4* o = (float4*)(out + (size_t)t * H);
    for (int i = threadIdx.x; i < H / 4; i += blockDim.x) {
        uint2 a = y0[i], b = y1[i], c = ys[i];
        float2 a0 = __half22float2(*(__half2*)&a.x), a1 = __half22float2(*(__half2*)&a.y);
        float2 b0 = __half22float2(*(__half2*)&b.x), b1 = __half22float2(*(__half2*)&b.y);
        float2 c0 = __half22float2(*(__half2*)&c.x), c1 = __half22float2(*(__half2*)&c.y);
        float4 r;
        r.x = fmaf(w0, a0.x, fmaf(w1, b0.x, c0.x));
        r.y = fmaf(w0, a0.y, fmaf(w1, b0.y, c0.y));
        r.z = fmaf(w0, a1.x, fmaf(w1, b1.x, c1.x));
        r.w = fmaf(w0, a1.y, fmaf(w1, b1.y, c1.y));
        o[i] = r;
    }
}

// ---------------- stream/event context (created at static init, reused) ------------
struct ForkCtx {
    cudaStream_t sB;
    cudaEvent_t evF, ev1, ev2;
    ForkCtx() {
        cudaStreamCreateWithFlags(&sB, cudaStreamNonBlocking);
        cudaEventCreateWithFlags(&evF, cudaEventDisableTiming);
        cudaEventCreateWithFlags(&ev1, cudaEventDisableTiming);
        cudaEventCreateWithFlags(&ev2, cudaEventDisableTiming);
    }
};
static ForkCtx g_fork;

// ---------------- host launcher (graph-captured with stream fork) -------------------
extern "C" void kernel_launch(void* const* d_in, const int* in_sizes, int n_in,
                              void* d_out, int out_size) {
    const float* x   = (const float*)d_in[0];
    const float* gw  = (const float*)d_in[1];
    const float* wg  = (const float*)d_in[2];
    const float* wu  = (const float*)d_in[3];
    const float* wd  = (const float*)d_in[4];
    const float* swg = (const float*)d_in[5];
    const float* swu = (const float*)d_in[6];
    const float* swd = (const float*)d_in[7];
    float* out = (float*)d_out;

    cudaFuncSetAttribute(k_gemm1, cudaFuncAttributeMaxDynamicSharedMemorySize, SMEM_TOTAL);
    cudaFuncSetAttribute(k_gemm2, cudaFuncAttributeMaxDynamicSharedMemorySize, SMEM_TOTAL);

    // fork side stream off the capture (default) stream
    cudaEventRecord(g_fork.evF, 0);
    cudaStreamWaitEvent(g_fork.sB, g_fork.evF, 0);

    // side branch: all weight conversions + shared gather at streaming occupancy
    k_cvtA<<<NB_SHG + NB_SCV + NB_RCV, 128, 0, g_fork.sB>>>(x, wg, wu, swg, swu);
    cudaEventRecord(g_fork.ev1, g_fork.sB);
    k_cvtB<<<512, 256, 0, g_fork.sB>>>(wd, swd);
    cudaEventRecord(g_fork.ev2, g_fork.sB);

    // main branch
    k_gate<<<T / 4, 128>>>(x, gw);
    k_scan<<<1, 1>>>();
    k_gather<<<2 * T, 256>>>(x);
    cudaStreamWaitEvent(0, g_fork.ev1, 0);     // gate/up weights + shared gather ready
    k_gemm1<<<dim3(2 * FS / BN, 32, E + 1), 256, SMEM_TOTAL>>>();
    cudaStreamWaitEvent(0, g_fork.ev2, 0);     // down weights ready
    k_gemm2<<<dim3(H / BN, 32, E + 1), 256, SMEM_TOTAL>>>();
    k_comb<<<T, 256>>>(out);
}